// round 2
// baseline (speedup 1.0000x reference)
#include <cuda_runtime.h>

#define NB     16
#define CC     64
#define WHT    16384
#define CWH    (CC * WHT)
#define SPLITS 16

// Scratch (device globals; allocation is forbidden)
__device__ float g_gram_part[2 * NB * SPLITS * CC * CC];   // 8 MB, per-split partial grams
__device__ float g_sums_part[2 * NB * SPLITS * 4 * CC];    // per-(split,group) channel sums
__device__ float g_logits[NB * 2 * CC * CC];
__device__ float g_att[NB * 2 * CC * CC];

typedef unsigned long long u64;

__device__ __forceinline__ u64 splat2(float x) {
    u64 r; unsigned xi = __float_as_uint(x);
    asm("mov.b64 %0, {%1, %1};" : "=l"(r) : "r"(xi));
    return r;
}
__device__ __forceinline__ void ffma2(u64 &acc, u64 a, u64 b) {
    asm("fma.rn.f32x2 %0, %1, %2, %3;" : "=l"(acc) : "l"(a), "l"(b), "l"(acc));
}
__device__ __forceinline__ void add2(u64 &acc, u64 a) {
    asm("add.rn.f32x2 %0, %1, %2;" : "=l"(acc) : "l"(a), "l"(acc));
}
__device__ __forceinline__ float2 unpk(u64 v) {
    unsigned lo, hi;
    asm("mov.b64 {%0, %1}, %2;" : "=r"(lo), "=r"(hi) : "l"(v));
    return make_float2(__uint_as_float(lo), __uint_as_float(hi));
}

// ---------------------------------------------------------------------------
// Kernel 1: gram partials. grid = 2*16*16 = 512 blocks, 256 threads.
// Block = (mat, n, split): 1024 pixels. 4 groups of 64 threads, each group
// owns 256 pixels; per-thread 8x8 register tile of the 64x64 gram.
// Groups reduced in-block; one clean partial written per block. No atomics.
// ---------------------------------------------------------------------------
__global__ void __launch_bounds__(256) gram_kernel(const float* __restrict__ xR,
                                                   const float* __restrict__ xT) {
    int b = blockIdx.x;
    int split = b & 15; b >>= 4;
    int n = b & 15;
    int mat = b >> 4;
    const float* src = (mat ? xT : xR) + n * CWH;

    __shared__ float stage[4][16][64];   // 16 KB: [group][pixel][channel]

    int tid = threadIdx.x;
    int g = tid >> 6;          // group 0..3
    int t = tid & 63;          // thread-in-group = channel for loading
    int ri = t >> 3;           // row tile 8*ri..8*ri+7
    int cj = t & 7;            // col tile 8*cj..8*cj+7
    float (*smg)[64] = stage[g];
    int pb = split * 1024 + g * 256;

    u64 acc[8][4];
#pragma unroll
    for (int i = 0; i < 8; i++)
#pragma unroll
        for (int j = 0; j < 4; j++) acc[i][j] = 0ull;
    float csum = 0.0f;

    const float* rowp = src + t * WHT + pb;
    // prefetch tile 0 (16 pixels of this thread's channel)
    float4 v[4];
#pragma unroll
    for (int i = 0; i < 4; i++) v[i] = *(const float4*)(rowp + 4 * i);

    for (int tile = 0; tile < 16; tile++) {
        __syncthreads();
#pragma unroll
        for (int i = 0; i < 4; i++) {
            smg[4 * i + 0][t] = v[i].x;
            smg[4 * i + 1][t] = v[i].y;
            smg[4 * i + 2][t] = v[i].z;
            smg[4 * i + 3][t] = v[i].w;
            csum += (v[i].x + v[i].y) + (v[i].z + v[i].w);
        }
        __syncthreads();
        if (tile < 15) {
            const float* nxt = rowp + (tile + 1) * 16;
#pragma unroll
            for (int i = 0; i < 4; i++) v[i] = *(const float4*)(nxt + 4 * i);
        }
#pragma unroll 8
        for (int p = 0; p < 16; p++) {
            const float* row = smg[p];
            float4 a0 = *(const float4*)&row[8 * ri];
            float4 a1 = *(const float4*)&row[8 * ri + 4];
            ulonglong2 bl = *(const ulonglong2*)&row[8 * cj];
            ulonglong2 bh = *(const ulonglong2*)&row[8 * cj + 4];
            u64 B0 = bl.x, B1 = bl.y, B2 = bh.x, B3 = bh.y;
            u64 A;
            A = splat2(a0.x); ffma2(acc[0][0],A,B0); ffma2(acc[0][1],A,B1); ffma2(acc[0][2],A,B2); ffma2(acc[0][3],A,B3);
            A = splat2(a0.y); ffma2(acc[1][0],A,B0); ffma2(acc[1][1],A,B1); ffma2(acc[1][2],A,B2); ffma2(acc[1][3],A,B3);
            A = splat2(a0.z); ffma2(acc[2][0],A,B0); ffma2(acc[2][1],A,B1); ffma2(acc[2][2],A,B2); ffma2(acc[2][3],A,B3);
            A = splat2(a0.w); ffma2(acc[3][0],A,B0); ffma2(acc[3][1],A,B1); ffma2(acc[3][2],A,B2); ffma2(acc[3][3],A,B3);
            A = splat2(a1.x); ffma2(acc[4][0],A,B0); ffma2(acc[4][1],A,B1); ffma2(acc[4][2],A,B2); ffma2(acc[4][3],A,B3);
            A = splat2(a1.y); ffma2(acc[5][0],A,B0); ffma2(acc[5][1],A,B1); ffma2(acc[5][2],A,B2); ffma2(acc[5][3],A,B3);
            A = splat2(a1.z); ffma2(acc[6][0],A,B0); ffma2(acc[6][1],A,B1); ffma2(acc[6][2],A,B2); ffma2(acc[6][3],A,B3);
            A = splat2(a1.w); ffma2(acc[7][0],A,B0); ffma2(acc[7][1],A,B1); ffma2(acc[7][2],A,B2); ffma2(acc[7][3],A,B3);
        }
    }

    // inter-group reduce (reuse staging smem as u64 buffer: 2048 u64 = 16 KB)
    u64* red = (u64*)stage;
    __syncthreads();
    if (g >= 2) {
        u64* dst = red + ((g - 2) * 64 + t) * 16;   // half each: store 16 of 32, two passes
        // two passes to fit 16 KB: first 16 u64
#pragma unroll
        for (int k = 0; k < 16; k++) dst[k] = acc[k >> 2][k & 3];
    }
    __syncthreads();
    if (g < 2) {
        const u64* s2 = red + (g * 64 + t) * 16;
#pragma unroll
        for (int k = 0; k < 16; k++) add2(acc[k >> 2][k & 3], s2[k]);
    }
    __syncthreads();
    if (g >= 2) {
        u64* dst = red + ((g - 2) * 64 + t) * 16;
#pragma unroll
        for (int k = 0; k < 16; k++) dst[k] = acc[(k + 16) >> 2][(k + 16) & 3];
    }
    __syncthreads();
    if (g < 2) {
        const u64* s2 = red + (g * 64 + t) * 16;
#pragma unroll
        for (int k = 0; k < 16; k++) add2(acc[(k + 16) >> 2][(k + 16) & 3], s2[k]);
    }
    __syncthreads();
    if (g == 1) {
        u64* dst = red + t * 32;
#pragma unroll
        for (int k = 0; k < 32; k++) dst[k] = acc[k >> 2][k & 3];
    }
    __syncthreads();
    if (g == 0) {
        const u64* s2 = red + t * 32;
#pragma unroll
        for (int k = 0; k < 32; k++) add2(acc[k >> 2][k & 3], s2[k]);
        float* gb = g_gram_part + ((mat * NB + n) * SPLITS + split) * 4096;
#pragma unroll
        for (int i = 0; i < 8; i++) {
            ulonglong2 lo, hi;
            lo.x = acc[i][0]; lo.y = acc[i][1];
            hi.x = acc[i][2]; hi.y = acc[i][3];
            ulonglong2* o = (ulonglong2*)&gb[(8 * ri + i) * 64 + 8 * cj];
            o[0] = lo; o[1] = hi;
        }
    }
    // per-channel sums (thread t = channel t within its group's pixel range)
    g_sums_part[(((mat * NB + n) * SPLITS + split) * 4 + g) * 64 + t] = csum;
}

// ---------------------------------------------------------------------------
// Kernel 2: logits  S = W G W^T + b u^T + u b^T + WH b b^T   (per n, per mat)
// grid = 32, 256 threads. Reduces the 16 gram partials + 64 sum partials.
// ---------------------------------------------------------------------------
__global__ void __launch_bounds__(256) logits_kernel(const float* __restrict__ WR,
                                                     const float* __restrict__ bR,
                                                     const float* __restrict__ WT,
                                                     const float* __restrict__ bT) {
    int n = blockIdx.x & 15;
    int mat = blockIdx.x >> 4;
    const float* W  = mat ? WT : WR;
    const float* bv = mat ? bT : bR;

    __shared__ float sW[64][64];
    __shared__ float sGM[64][65];
    __shared__ float sb[64], ssum[64], su[64];

    int tid = threadIdx.x;
    // load W (vectorized)
    for (int i = tid; i < 1024; i += 256)
        ((float4*)&sW[0][0])[i] = ((const float4*)W)[i];

    // reduce 16 gram partials
    const float4* gp = (const float4*)(g_gram_part + (mat * NB + n) * SPLITS * 4096);
    for (int i = tid; i < 1024; i += 256) {
        float4 a = gp[i];
#pragma unroll
        for (int s = 1; s < SPLITS; s++) {
            float4 b = gp[s * 1024 + i];
            a.x += b.x; a.y += b.y; a.z += b.z; a.w += b.w;
        }
        int row = i >> 4, col = (i & 15) * 4;
        sGM[row][col] = a.x; sGM[row][col + 1] = a.y;
        sGM[row][col + 2] = a.z; sGM[row][col + 3] = a.w;
    }
    if (tid < 64) {
        sb[tid] = bv[tid];
        const float* sp = g_sums_part + (mat * NB + n) * SPLITS * 4 * 64 + tid;
        float s = 0.0f;
#pragma unroll
        for (int k = 0; k < SPLITS * 4; k++) s += sp[k * 64];
        ssum[tid] = s;
    }
    __syncthreads();

    if (tid < 64) {
        float u = 0.0f;
        for (int f = 0; f < 64; f++) u += sW[tid][f] * ssum[f];
        su[tid] = u;
    }

    int r = tid >> 4, q = tid & 15;
    float acc[4][4];
#pragma unroll
    for (int i = 0; i < 4; i++)
#pragma unroll
        for (int j = 0; j < 4; j++) acc[i][j] = 0.0f;
    // M = W * G
    for (int f = 0; f < 64; f++) {
        float wv[4], gv[4];
#pragma unroll
        for (int i = 0; i < 4; i++) wv[i] = sW[4 * r + i][f];
#pragma unroll
        for (int j = 0; j < 4; j++) gv[j] = sGM[f][4 * q + j];
#pragma unroll
        for (int i = 0; i < 4; i++)
#pragma unroll
            for (int j = 0; j < 4; j++) acc[i][j] = fmaf(wv[i], gv[j], acc[i][j]);
    }
    __syncthreads();
#pragma unroll
    for (int i = 0; i < 4; i++)
#pragma unroll
        for (int j = 0; j < 4; j++) sGM[4 * r + i][4 * q + j] = acc[i][j];
    __syncthreads();

    // S = M * W^T
#pragma unroll
    for (int i = 0; i < 4; i++)
#pragma unroll
        for (int j = 0; j < 4; j++) acc[i][j] = 0.0f;
    for (int e = 0; e < 64; e++) {
        float mv[4], wv[4];
#pragma unroll
        for (int i = 0; i < 4; i++) mv[i] = sGM[4 * r + i][e];
#pragma unroll
        for (int j = 0; j < 4; j++) wv[j] = sW[4 * q + j][e];
#pragma unroll
        for (int i = 0; i < 4; i++)
#pragma unroll
            for (int j = 0; j < 4; j++) acc[i][j] = fmaf(mv[i], wv[j], acc[i][j]);
    }

    float* lbase = g_logits + n * (2 * CC * CC);
#pragma unroll
    for (int i = 0; i < 4; i++) {
        int ci = 4 * r + i;
#pragma unroll
        for (int j = 0; j < 4; j++) {
            int dj = 4 * q + j;
            float L = acc[i][j] + sb[ci] * su[dj] + su[ci] * sb[dj]
                    + 16384.0f * sb[ci] * sb[dj];
            lbase[(mat * CC + ci) * CC + dj] = L;
        }
    }
}

// ---------------------------------------------------------------------------
// Kernel 3: softmax over 128 rows per (n, col). grid = 16, 256 threads.
// One global read, one __expf pass, all coalesced.
// ---------------------------------------------------------------------------
__global__ void __launch_bounds__(256) softmax_kernel() {
    __shared__ float sE[128][64];   // 32 KB
    __shared__ float sred[256];

    int n = blockIdx.x;
    int tid = threadIdx.x;
    int col = tid & 63, q = tid >> 6;
    const float* L = g_logits + n * 8192;

    float m = -3.0e38f;
    for (int k = 32 * q; k < 32 * q + 32; k++) {
        float v = L[k * 64 + col];     // coalesced
        sE[k][col] = v;
        m = fmaxf(m, v);
    }
    sred[tid] = m;
    __syncthreads();
    m = fmaxf(fmaxf(sred[col], sred[64 + col]),
              fmaxf(sred[128 + col], sred[192 + col]));
    __syncthreads();

    float s = 0.0f;
    for (int k = 32 * q; k < 32 * q + 32; k++) {
        float e = __expf(sE[k][col] - m);
        sE[k][col] = e;
        s += e;
    }
    sred[tid] = s;
    __syncthreads();
    s = (sred[col] + sred[64 + col]) + (sred[128 + col] + sred[192 + col]);
    float inv = 1.0f / s;

    float* A = g_att + n * 8192;
    for (int k = 32 * q; k < 32 * q + 32; k++)
        A[k * 64 + col] = sE[k][col] * inv;
}

// ---------------------------------------------------------------------------
// Kernel 4: out[n,c,p] = sum_k xcat[n,k,p] * att[n,k,c]
// grid = (WH/256, 16), 256 threads. Block tile: 64c x 256p, thread 8c x 8p.
// ---------------------------------------------------------------------------
__global__ void __launch_bounds__(256) out_kernel(const float* __restrict__ xR,
                                                  const float* __restrict__ xT,
                                                  float* __restrict__ out) {
    int n  = blockIdx.y;
    int pb = blockIdx.x * 256;

    __shared__ float att_s[128][64];   // 32 KB
    __shared__ float xs[16][256];      // 16 KB

    int tid = threadIdx.x;
    const float4* attp = (const float4*)(g_att + n * (2 * CC * CC));
#pragma unroll
    for (int i = 0; i < 8; i++)
        ((float4*)&att_s[0][0])[tid + i * 256] = attp[tid + i * 256];

    int ci = tid >> 5;     // 0..7  -> channels 8ci..8ci+7
    int pj = tid & 31;     // pixels {2pj,2pj+1} + 64s, s=0..3
    int kl = tid >> 4;     // 0..15 row for staging
    int pc = (tid & 15) * 16;

    u64 acc[8][4];
#pragma unroll
    for (int i = 0; i < 8; i++)
#pragma unroll
        for (int s = 0; s < 4; s++) acc[i][s] = 0ull;

    const float* baseR = xR + n * CWH + pb;
    const float* baseT = xT + n * CWH + pb;

    // prefetch k-tile 0
    float4 v[4];
    {
        const float* srcp = baseR + kl * WHT + pc;
#pragma unroll
        for (int i = 0; i < 4; i++) v[i] = *(const float4*)(srcp + 4 * i);
    }

    for (int kt = 0; kt < 8; kt++) {
        __syncthreads();
#pragma unroll
        for (int i = 0; i < 4; i++)
            *(float4*)&xs[kl][pc + 4 * i] = v[i];
        __syncthreads();
        if (kt < 7) {
            int kt2 = kt + 1;
            const float* src = (kt2 < 4) ? baseR : baseT;
            int kbase = (kt2 < 4) ? kt2 * 16 : (kt2 - 4) * 16;
            const float* srcp = src + (kbase + kl) * WHT + pc;
#pragma unroll
            for (int i = 0; i < 4; i++) v[i] = *(const float4*)(srcp + 4 * i);
        }
#pragma unroll 8
        for (int k = 0; k < 16; k++) {
            const float* ar = att_s[kt * 16 + k];
            float4 a0 = *(const float4*)&ar[8 * ci];
            float4 a1 = *(const float4*)&ar[8 * ci + 4];
            const float* xr = xs[k];
            u64 B0 = *(const u64*)&xr[2 * pj];
            u64 B1 = *(const u64*)&xr[2 * pj + 64];
            u64 B2 = *(const u64*)&xr[2 * pj + 128];
            u64 B3 = *(const u64*)&xr[2 * pj + 192];
            u64 A;
            A = splat2(a0.x); ffma2(acc[0][0],A,B0); ffma2(acc[0][1],A,B1); ffma2(acc[0][2],A,B2); ffma2(acc[0][3],A,B3);
            A = splat2(a0.y); ffma2(acc[1][0],A,B0); ffma2(acc[1][1],A,B1); ffma2(acc[1][2],A,B2); ffma2(acc[1][3],A,B3);
            A = splat2(a0.z); ffma2(acc[2][0],A,B0); ffma2(acc[2][1],A,B1); ffma2(acc[2][2],A,B2); ffma2(acc[2][3],A,B3);
            A = splat2(a0.w); ffma2(acc[3][0],A,B0); ffma2(acc[3][1],A,B1); ffma2(acc[3][2],A,B2); ffma2(acc[3][3],A,B3);
            A = splat2(a1.x); ffma2(acc[4][0],A,B0); ffma2(acc[4][1],A,B1); ffma2(acc[4][2],A,B2); ffma2(acc[4][3],A,B3);
            A = splat2(a1.y); ffma2(acc[5][0],A,B0); ffma2(acc[5][1],A,B1); ffma2(acc[5][2],A,B2); ffma2(acc[5][3],A,B3);
            A = splat2(a1.z); ffma2(acc[6][0],A,B0); ffma2(acc[6][1],A,B1); ffma2(acc[6][2],A,B2); ffma2(acc[6][3],A,B3);
            A = splat2(a1.w); ffma2(acc[7][0],A,B0); ffma2(acc[7][1],A,B1); ffma2(acc[7][2],A,B2); ffma2(acc[7][3],A,B3);
        }
    }

    float* ob = out + n * CWH + pb;
#pragma unroll
    for (int i = 0; i < 8; i++) {
        int c = 8 * ci + i;
#pragma unroll
        for (int s = 0; s < 4; s++) {
            float2 w = unpk(acc[i][s]);
            *(float2*)&ob[c * WHT + 2 * pj + 64 * s] = w;
        }
    }
}

// ---------------------------------------------------------------------------
extern "C" void kernel_launch(void* const* d_in, const int* in_sizes, int n_in,
                              void* d_out, int out_size) {
    const float* xR = (const float*)d_in[0];
    const float* xT = (const float*)d_in[1];
    const float* WR = (const float*)d_in[2];
    const float* bR = (const float*)d_in[3];
    const float* WT = (const float*)d_in[4];
    const float* bT = (const float*)d_in[5];
    float* out = (float*)d_out;

    gram_kernel<<<2 * NB * SPLITS, 256>>>(xR, xT);
    logits_kernel<<<2 * NB, 256>>>(WR, bR, WT, bT);
    softmax_kernel<<<NB, 256>>>();
    out_kernel<<<dim3(WHT / 256, NB), 256>>>(xR, xT, out);
}

// round 3
// speedup vs baseline: 1.0008x; 1.0008x over previous
#include <cuda_runtime.h>

#define NB     16
#define CC     64
#define WHT    16384
#define CWH    (CC * WHT)
#define SPLITS 16

// Scratch (device globals; allocation is forbidden)
__device__ float g_gram_part[2 * NB * SPLITS * CC * CC];   // 8 MB, per-split partial grams
__device__ float g_sums_part[2 * NB * SPLITS * 4 * CC];    // per-(split,group) channel sums
__device__ float g_logits[NB * 2 * CC * CC];
__device__ float g_att[NB * 2 * CC * CC];

typedef unsigned long long u64;

__device__ __forceinline__ u64 splat2(float x) {
    u64 r; unsigned xi = __float_as_uint(x);
    asm("mov.b64 %0, {%1, %1};" : "=l"(r) : "r"(xi));
    return r;
}
__device__ __forceinline__ void ffma2(u64 &acc, u64 a, u64 b) {
    asm("fma.rn.f32x2 %0, %1, %2, %3;" : "=l"(acc) : "l"(a), "l"(b), "l"(acc));
}
__device__ __forceinline__ void add2(u64 &acc, u64 a) {
    asm("add.rn.f32x2 %0, %1, %2;" : "=l"(acc) : "l"(a), "l"(acc));
}
__device__ __forceinline__ float2 unpk(u64 v) {
    unsigned lo, hi;
    asm("mov.b64 {%0, %1}, %2;" : "=r"(lo), "=r"(hi) : "l"(v));
    return make_float2(__uint_as_float(lo), __uint_as_float(hi));
}

// ---------------------------------------------------------------------------
// Kernel 1: gram partials. grid = 2*16*16 = 512 blocks, 256 threads.
// Block = (mat, n, split): 1024 pixels. 4 groups of 64 threads, each group
// owns 256 pixels; per-thread 8x8 register tile of the 64x64 gram.
// Groups reduced in-block; one clean partial written per block. No atomics.
// ---------------------------------------------------------------------------
__global__ void __launch_bounds__(256) gram_kernel(const float* __restrict__ xR,
                                                   const float* __restrict__ xT) {
    int b = blockIdx.x;
    int split = b & 15; b >>= 4;
    int n = b & 15;
    int mat = b >> 4;
    const float* src = (mat ? xT : xR) + n * CWH;

    __shared__ float stage[4][16][64];   // 16 KB: [group][pixel][channel]

    int tid = threadIdx.x;
    int g = tid >> 6;          // group 0..3
    int t = tid & 63;          // thread-in-group = channel for loading
    int ri = t >> 3;           // row tile 8*ri..8*ri+7
    int cj = t & 7;            // col tile 8*cj..8*cj+7
    float (*smg)[64] = stage[g];
    int pb = split * 1024 + g * 256;

    u64 acc[8][4];
#pragma unroll
    for (int i = 0; i < 8; i++)
#pragma unroll
        for (int j = 0; j < 4; j++) acc[i][j] = 0ull;
    float csum = 0.0f;

    const float* rowp = src + t * WHT + pb;
    // prefetch tile 0 (16 pixels of this thread's channel)
    float4 v[4];
#pragma unroll
    for (int i = 0; i < 4; i++) v[i] = *(const float4*)(rowp + 4 * i);

    for (int tile = 0; tile < 16; tile++) {
        __syncthreads();
#pragma unroll
        for (int i = 0; i < 4; i++) {
            smg[4 * i + 0][t] = v[i].x;
            smg[4 * i + 1][t] = v[i].y;
            smg[4 * i + 2][t] = v[i].z;
            smg[4 * i + 3][t] = v[i].w;
            csum += (v[i].x + v[i].y) + (v[i].z + v[i].w);
        }
        __syncthreads();
        if (tile < 15) {
            const float* nxt = rowp + (tile + 1) * 16;
#pragma unroll
            for (int i = 0; i < 4; i++) v[i] = *(const float4*)(nxt + 4 * i);
        }
#pragma unroll 8
        for (int p = 0; p < 16; p++) {
            const float* row = smg[p];
            float4 a0 = *(const float4*)&row[8 * ri];
            float4 a1 = *(const float4*)&row[8 * ri + 4];
            ulonglong2 bl = *(const ulonglong2*)&row[8 * cj];
            ulonglong2 bh = *(const ulonglong2*)&row[8 * cj + 4];
            u64 B0 = bl.x, B1 = bl.y, B2 = bh.x, B3 = bh.y;
            u64 A;
            A = splat2(a0.x); ffma2(acc[0][0],A,B0); ffma2(acc[0][1],A,B1); ffma2(acc[0][2],A,B2); ffma2(acc[0][3],A,B3);
            A = splat2(a0.y); ffma2(acc[1][0],A,B0); ffma2(acc[1][1],A,B1); ffma2(acc[1][2],A,B2); ffma2(acc[1][3],A,B3);
            A = splat2(a0.z); ffma2(acc[2][0],A,B0); ffma2(acc[2][1],A,B1); ffma2(acc[2][2],A,B2); ffma2(acc[2][3],A,B3);
            A = splat2(a0.w); ffma2(acc[3][0],A,B0); ffma2(acc[3][1],A,B1); ffma2(acc[3][2],A,B2); ffma2(acc[3][3],A,B3);
            A = splat2(a1.x); ffma2(acc[4][0],A,B0); ffma2(acc[4][1],A,B1); ffma2(acc[4][2],A,B2); ffma2(acc[4][3],A,B3);
            A = splat2(a1.y); ffma2(acc[5][0],A,B0); ffma2(acc[5][1],A,B1); ffma2(acc[5][2],A,B2); ffma2(acc[5][3],A,B3);
            A = splat2(a1.z); ffma2(acc[6][0],A,B0); ffma2(acc[6][1],A,B1); ffma2(acc[6][2],A,B2); ffma2(acc[6][3],A,B3);
            A = splat2(a1.w); ffma2(acc[7][0],A,B0); ffma2(acc[7][1],A,B1); ffma2(acc[7][2],A,B2); ffma2(acc[7][3],A,B3);
        }
    }

    // inter-group reduce (reuse staging smem as u64 buffer: 2048 u64 = 16 KB)
    u64* red = (u64*)stage;
    __syncthreads();
    if (g >= 2) {
        u64* dst = red + ((g - 2) * 64 + t) * 16;   // half each: store 16 of 32, two passes
        // two passes to fit 16 KB: first 16 u64
#pragma unroll
        for (int k = 0; k < 16; k++) dst[k] = acc[k >> 2][k & 3];
    }
    __syncthreads();
    if (g < 2) {
        const u64* s2 = red + (g * 64 + t) * 16;
#pragma unroll
        for (int k = 0; k < 16; k++) add2(acc[k >> 2][k & 3], s2[k]);
    }
    __syncthreads();
    if (g >= 2) {
        u64* dst = red + ((g - 2) * 64 + t) * 16;
#pragma unroll
        for (int k = 0; k < 16; k++) dst[k] = acc[(k + 16) >> 2][(k + 16) & 3];
    }
    __syncthreads();
    if (g < 2) {
        const u64* s2 = red + (g * 64 + t) * 16;
#pragma unroll
        for (int k = 0; k < 16; k++) add2(acc[(k + 16) >> 2][(k + 16) & 3], s2[k]);
    }
    __syncthreads();
    if (g == 1) {
        u64* dst = red + t * 32;
#pragma unroll
        for (int k = 0; k < 32; k++) dst[k] = acc[k >> 2][k & 3];
    }
    __syncthreads();
    if (g == 0) {
        const u64* s2 = red + t * 32;
#pragma unroll
        for (int k = 0; k < 32; k++) add2(acc[k >> 2][k & 3], s2[k]);
        float* gb = g_gram_part + ((mat * NB + n) * SPLITS + split) * 4096;
#pragma unroll
        for (int i = 0; i < 8; i++) {
            ulonglong2 lo, hi;
            lo.x = acc[i][0]; lo.y = acc[i][1];
            hi.x = acc[i][2]; hi.y = acc[i][3];
            ulonglong2* o = (ulonglong2*)&gb[(8 * ri + i) * 64 + 8 * cj];
            o[0] = lo; o[1] = hi;
        }
    }
    // per-channel sums (thread t = channel t within its group's pixel range)
    g_sums_part[(((mat * NB + n) * SPLITS + split) * 4 + g) * 64 + t] = csum;
}

// ---------------------------------------------------------------------------
// Kernel 2: logits  S = W G W^T + b u^T + u b^T + WH b b^T   (per n, per mat)
// grid = 32, 256 threads. Reduces the 16 gram partials + 64 sum partials.
// ---------------------------------------------------------------------------
__global__ void __launch_bounds__(256) logits_kernel(const float* __restrict__ WR,
                                                     const float* __restrict__ bR,
                                                     const float* __restrict__ WT,
                                                     const float* __restrict__ bT) {
    int n = blockIdx.x & 15;
    int mat = blockIdx.x >> 4;
    const float* W  = mat ? WT : WR;
    const float* bv = mat ? bT : bR;

    __shared__ float sW[64][64];
    __shared__ float sGM[64][65];
    __shared__ float sb[64], ssum[64], su[64];

    int tid = threadIdx.x;
    // load W (vectorized)
    for (int i = tid; i < 1024; i += 256)
        ((float4*)&sW[0][0])[i] = ((const float4*)W)[i];

    // reduce 16 gram partials
    const float4* gp = (const float4*)(g_gram_part + (mat * NB + n) * SPLITS * 4096);
    for (int i = tid; i < 1024; i += 256) {
        float4 a = gp[i];
#pragma unroll
        for (int s = 1; s < SPLITS; s++) {
            float4 b = gp[s * 1024 + i];
            a.x += b.x; a.y += b.y; a.z += b.z; a.w += b.w;
        }
        int row = i >> 4, col = (i & 15) * 4;
        sGM[row][col] = a.x; sGM[row][col + 1] = a.y;
        sGM[row][col + 2] = a.z; sGM[row][col + 3] = a.w;
    }
    if (tid < 64) {
        sb[tid] = bv[tid];
        const float* sp = g_sums_part + (mat * NB + n) * SPLITS * 4 * 64 + tid;
        float s = 0.0f;
#pragma unroll
        for (int k = 0; k < SPLITS * 4; k++) s += sp[k * 64];
        ssum[tid] = s;
    }
    __syncthreads();

    if (tid < 64) {
        float u = 0.0f;
        for (int f = 0; f < 64; f++) u += sW[tid][f] * ssum[f];
        su[tid] = u;
    }

    int r = tid >> 4, q = tid & 15;
    float acc[4][4];
#pragma unroll
    for (int i = 0; i < 4; i++)
#pragma unroll
        for (int j = 0; j < 4; j++) acc[i][j] = 0.0f;
    // M = W * G
    for (int f = 0; f < 64; f++) {
        float wv[4], gv[4];
#pragma unroll
        for (int i = 0; i < 4; i++) wv[i] = sW[4 * r + i][f];
#pragma unroll
        for (int j = 0; j < 4; j++) gv[j] = sGM[f][4 * q + j];
#pragma unroll
        for (int i = 0; i < 4; i++)
#pragma unroll
            for (int j = 0; j < 4; j++) acc[i][j] = fmaf(wv[i], gv[j], acc[i][j]);
    }
    __syncthreads();
#pragma unroll
    for (int i = 0; i < 4; i++)
#pragma unroll
        for (int j = 0; j < 4; j++) sGM[4 * r + i][4 * q + j] = acc[i][j];
    __syncthreads();

    // S = M * W^T
#pragma unroll
    for (int i = 0; i < 4; i++)
#pragma unroll
        for (int j = 0; j < 4; j++) acc[i][j] = 0.0f;
    for (int e = 0; e < 64; e++) {
        float mv[4], wv[4];
#pragma unroll
        for (int i = 0; i < 4; i++) mv[i] = sGM[4 * r + i][e];
#pragma unroll
        for (int j = 0; j < 4; j++) wv[j] = sW[4 * q + j][e];
#pragma unroll
        for (int i = 0; i < 4; i++)
#pragma unroll
            for (int j = 0; j < 4; j++) acc[i][j] = fmaf(mv[i], wv[j], acc[i][j]);
    }

    float* lbase = g_logits + n * (2 * CC * CC);
#pragma unroll
    for (int i = 0; i < 4; i++) {
        int ci = 4 * r + i;
#pragma unroll
        for (int j = 0; j < 4; j++) {
            int dj = 4 * q + j;
            float L = acc[i][j] + sb[ci] * su[dj] + su[ci] * sb[dj]
                    + 16384.0f * sb[ci] * sb[dj];
            lbase[(mat * CC + ci) * CC + dj] = L;
        }
    }
}

// ---------------------------------------------------------------------------
// Kernel 3: softmax over 128 rows per (n, col). grid = 16, 256 threads.
// One global read, one __expf pass, all coalesced.
// ---------------------------------------------------------------------------
__global__ void __launch_bounds__(256) softmax_kernel() {
    __shared__ float sE[128][64];   // 32 KB
    __shared__ float sred[256];

    int n = blockIdx.x;
    int tid = threadIdx.x;
    int col = tid & 63, q = tid >> 6;
    const float* L = g_logits + n * 8192;

    float m = -3.0e38f;
    for (int k = 32 * q; k < 32 * q + 32; k++) {
        float v = L[k * 64 + col];     // coalesced
        sE[k][col] = v;
        m = fmaxf(m, v);
    }
    sred[tid] = m;
    __syncthreads();
    m = fmaxf(fmaxf(sred[col], sred[64 + col]),
              fmaxf(sred[128 + col], sred[192 + col]));
    __syncthreads();

    float s = 0.0f;
    for (int k = 32 * q; k < 32 * q + 32; k++) {
        float e = __expf(sE[k][col] - m);
        sE[k][col] = e;
        s += e;
    }
    sred[tid] = s;
    __syncthreads();
    s = (sred[col] + sred[64 + col]) + (sred[128 + col] + sred[192 + col]);
    float inv = 1.0f / s;

    float* A = g_att + n * 8192;
    for (int k = 32 * q; k < 32 * q + 32; k++)
        A[k * 64 + col] = sE[k][col] * inv;
}

// ---------------------------------------------------------------------------
// Kernel 4: out[n,c,p] = sum_k xcat[n,k,p] * att[n,k,c]
// grid = (WH/256, 16), 256 threads. Block tile: 64c x 256p, thread 8c x 8p.
// ---------------------------------------------------------------------------
__global__ void __launch_bounds__(256) out_kernel(const float* __restrict__ xR,
                                                  const float* __restrict__ xT,
                                                  float* __restrict__ out) {
    int n  = blockIdx.y;
    int pb = blockIdx.x * 256;

    __shared__ float att_s[128][64];   // 32 KB
    __shared__ float xs[16][256];      // 16 KB

    int tid = threadIdx.x;
    const float4* attp = (const float4*)(g_att + n * (2 * CC * CC));
#pragma unroll
    for (int i = 0; i < 8; i++)
        ((float4*)&att_s[0][0])[tid + i * 256] = attp[tid + i * 256];

    int ci = tid >> 5;     // 0..7  -> channels 8ci..8ci+7
    int pj = tid & 31;     // pixels {2pj,2pj+1} + 64s, s=0..3
    int kl = tid >> 4;     // 0..15 row for staging
    int pc = (tid & 15) * 16;

    u64 acc[8][4];
#pragma unroll
    for (int i = 0; i < 8; i++)
#pragma unroll
        for (int s = 0; s < 4; s++) acc[i][s] = 0ull;

    const float* baseR = xR + n * CWH + pb;
    const float* baseT = xT + n * CWH + pb;

    // prefetch k-tile 0
    float4 v[4];
    {
        const float* srcp = baseR + kl * WHT + pc;
#pragma unroll
        for (int i = 0; i < 4; i++) v[i] = *(const float4*)(srcp + 4 * i);
    }

    for (int kt = 0; kt < 8; kt++) {
        __syncthreads();
#pragma unroll
        for (int i = 0; i < 4; i++)
            *(float4*)&xs[kl][pc + 4 * i] = v[i];
        __syncthreads();
        if (kt < 7) {
            int kt2 = kt + 1;
            const float* src = (kt2 < 4) ? baseR : baseT;
            int kbase = (kt2 < 4) ? kt2 * 16 : (kt2 - 4) * 16;
            const float* srcp = src + (kbase + kl) * WHT + pc;
#pragma unroll
            for (int i = 0; i < 4; i++) v[i] = *(const float4*)(srcp + 4 * i);
        }
#pragma unroll 8
        for (int k = 0; k < 16; k++) {
            const float* ar = att_s[kt * 16 + k];
            float4 a0 = *(const float4*)&ar[8 * ci];
            float4 a1 = *(const float4*)&ar[8 * ci + 4];
            const float* xr = xs[k];
            u64 B0 = *(const u64*)&xr[2 * pj];
            u64 B1 = *(const u64*)&xr[2 * pj + 64];
            u64 B2 = *(const u64*)&xr[2 * pj + 128];
            u64 B3 = *(const u64*)&xr[2 * pj + 192];
            u64 A;
            A = splat2(a0.x); ffma2(acc[0][0],A,B0); ffma2(acc[0][1],A,B1); ffma2(acc[0][2],A,B2); ffma2(acc[0][3],A,B3);
            A = splat2(a0.y); ffma2(acc[1][0],A,B0); ffma2(acc[1][1],A,B1); ffma2(acc[1][2],A,B2); ffma2(acc[1][3],A,B3);
            A = splat2(a0.z); ffma2(acc[2][0],A,B0); ffma2(acc[2][1],A,B1); ffma2(acc[2][2],A,B2); ffma2(acc[2][3],A,B3);
            A = splat2(a0.w); ffma2(acc[3][0],A,B0); ffma2(acc[3][1],A,B1); ffma2(acc[3][2],A,B2); ffma2(acc[3][3],A,B3);
            A = splat2(a1.x); ffma2(acc[4][0],A,B0); ffma2(acc[4][1],A,B1); ffma2(acc[4][2],A,B2); ffma2(acc[4][3],A,B3);
            A = splat2(a1.y); ffma2(acc[5][0],A,B0); ffma2(acc[5][1],A,B1); ffma2(acc[5][2],A,B2); ffma2(acc[5][3],A,B3);
            A = splat2(a1.z); ffma2(acc[6][0],A,B0); ffma2(acc[6][1],A,B1); ffma2(acc[6][2],A,B2); ffma2(acc[6][3],A,B3);
            A = splat2(a1.w); ffma2(acc[7][0],A,B0); ffma2(acc[7][1],A,B1); ffma2(acc[7][2],A,B2); ffma2(acc[7][3],A,B3);
        }
    }

    float* ob = out + n * CWH + pb;
#pragma unroll
    for (int i = 0; i < 8; i++) {
        int c = 8 * ci + i;
#pragma unroll
        for (int s = 0; s < 4; s++) {
            float2 w = unpk(acc[i][s]);
            *(float2*)&ob[c * WHT + 2 * pj + 64 * s] = w;
        }
    }
}

// ---------------------------------------------------------------------------
extern "C" void kernel_launch(void* const* d_in, const int* in_sizes, int n_in,
                              void* d_out, int out_size) {
    const float* xR = (const float*)d_in[0];
    const float* xT = (const float*)d_in[1];
    const float* WR = (const float*)d_in[2];
    const float* bR = (const float*)d_in[3];
    const float* WT = (const float*)d_in[4];
    const float* bT = (const float*)d_in[5];
    float* out = (float*)d_out;

    gram_kernel<<<2 * NB * SPLITS, 256>>>(xR, xT);
    logits_kernel<<<2 * NB, 256>>>(WR, bR, WT, bT);
    softmax_kernel<<<NB, 256>>>();
    out_kernel<<<dim3(WHT / 256, NB), 256>>>(xR, xT, out);
}

// round 6
// speedup vs baseline: 1.2634x; 1.2624x over previous
#include <cuda_runtime.h>
#include <cstdint>

#define NB     16
#define CC     64
#define WHT    16384
#define CWH    (CC * WHT)
#define SPLITS 32

// Scratch (device globals; allocation is forbidden)
__device__ float g_gram_part[2 * NB * SPLITS * CC * CC];   // 16.7 MB partial grams
__device__ float g_sums_part[2 * NB * SPLITS * CC];
__device__ float g_logits[NB * 2 * CC * CC];
__device__ float g_att[NB * 2 * CC * CC];

typedef unsigned long long u64;

__device__ __forceinline__ u64 splat2(float x) {
    u64 r; unsigned xi = __float_as_uint(x);
    asm("mov.b64 %0, {%1, %1};" : "=l"(r) : "r"(xi));
    return r;
}
__device__ __forceinline__ void ffma2(u64 &acc, u64 a, u64 b) {
    asm("fma.rn.f32x2 %0, %1, %2, %3;" : "=l"(acc) : "l"(a), "l"(b), "l"(acc));
}
__device__ __forceinline__ float2 unpk(u64 v) {
    unsigned lo, hi;
    asm("mov.b64 {%0, %1}, %2;" : "=r"(lo), "=r"(hi) : "l"(v));
    return make_float2(__uint_as_float(lo), __uint_as_float(hi));
}
__device__ __forceinline__ uint32_t smem_u32(const void* p) {
    uint32_t a;
    asm("{ .reg .u64 t; cvta.to.shared.u64 t, %1; cvt.u32.u64 %0, t; }" : "=r"(a) : "l"(p));
    return a;
}
__device__ __forceinline__ uint32_t cvt_tf32(float x) {
    uint32_t r;
    asm("cvt.rna.tf32.f32 %0, %1;" : "=r"(r) : "f"(x));
    return r;
}
__device__ __forceinline__ void ldsm4(uint32_t* r, uint32_t addr) {
    asm volatile("ldmatrix.sync.aligned.m8n8.x4.shared.b16 {%0,%1,%2,%3}, [%4];"
                 : "=r"(r[0]), "=r"(r[1]), "=r"(r[2]), "=r"(r[3]) : "r"(addr));
}
__device__ __forceinline__ void mma8(float* d, const uint32_t* a, const uint32_t* b) {
    asm volatile(
        "mma.sync.aligned.m16n8k8.row.col.f32.tf32.tf32.f32 "
        "{%0,%1,%2,%3}, {%4,%5,%6,%7}, {%8,%9}, {%0,%1,%2,%3};"
        : "+f"(d[0]), "+f"(d[1]), "+f"(d[2]), "+f"(d[3])
        : "r"(a[0]), "r"(a[1]), "r"(a[2]), "r"(a[3]), "r"(b[0]), "r"(b[1]));
}

// ---------------------------------------------------------------------------
// Kernel 1: gram partials via mma.sync tf32 with hi/lo splitting.
// grid = 2*16*32 = 1024 blocks (mat, n, split of 512 pixels), 128 threads.
// smem Y buffer: 128 rows (0-63 hi, 64-127 lo) x 32 px, row stride 36 floats.
// Warp tile 64x32: 4 m-tiles x 4 n-tiles, 3 streams (hh, hl, lh) = 48 mma/k8.
// 2 substreams (warp pairs on alternating 32-px chunks) reduced in-block.
// ---------------------------------------------------------------------------
__global__ void __launch_bounds__(128) gram_mma_kernel(const float* __restrict__ xR,
                                                       const float* __restrict__ xT) {
    int bid = blockIdx.x;
    int split = bid & 31;
    int n = (bid >> 5) & 15;
    int mat = bid >> 9;
    const float* src = (mat ? xT : xR) + n * CWH;

    __shared__ uint32_t sY[2][128 * 36];   // 36864 B

    int tid = threadIdx.x;
    int w = tid >> 5;
    int lane = tid & 31;
    int wk = w >> 1;           // substream (buffer index to consume)
    int wn = w & 1;            // n-half
    int ncol = wn * 32;

    // staging mapping: channel sc, pixel-half sj (-> buffer sj)
    int sc = tid >> 1;
    int sj = tid & 1;
    const float* gsrc = src + sc * WHT + split * 512 + sj * 32;

    // ldmatrix per-lane address components
    int q  = lane >> 3;
    int r8 = lane & 7;
    int a_row  = r8 + ((q & 1) << 3);      // A: m0=a0(r0-7,c0) m1=a1(r8-15,c0) m2=a2(r0-7,c4) m3=a3
    int a_colb = (q >> 1) << 4;
    int b_row  = r8 + ((q >> 1) << 3);     // B: m0=b0(nt0) m1=b1(nt0) m2=b0(nt1) m3=b1(nt1)
    int b_colb = (q & 1) << 4;

    float acc[4][4][4];
#pragma unroll
    for (int i = 0; i < 4; i++)
#pragma unroll
        for (int j = 0; j < 4; j++)
#pragma unroll
            for (int c = 0; c < 4; c++) acc[i][j][c] = 0.0f;
    float csum = 0.0f;

    uint32_t buf0 = smem_u32(sY[0]);
    uint32_t buf1 = smem_u32(sY[1]);
    uint32_t mybuf = wk ? buf1 : buf0;
    uint32_t stbuf = sj ? buf1 : buf0;
    uint32_t sb_hi = stbuf + sc * 144;
    uint32_t sb_lo = sb_hi + 64 * 144;

#pragma unroll 1
    for (int t = 0; t < 8; t++) {
        __syncthreads();
        const float4* p = (const float4*)(gsrc + t * 64);
#pragma unroll
        for (int i = 0; i < 8; i++) {
            float4 v = p[i];
            csum += (v.x + v.y) + (v.z + v.w);
            uint32_t hx = cvt_tf32(v.x), hy = cvt_tf32(v.y);
            uint32_t hz = cvt_tf32(v.z), hw = cvt_tf32(v.w);
            uint32_t lx = cvt_tf32(v.x - __uint_as_float(hx));
            uint32_t ly = cvt_tf32(v.y - __uint_as_float(hy));
            uint32_t lz = cvt_tf32(v.z - __uint_as_float(hz));
            uint32_t lw = cvt_tf32(v.w - __uint_as_float(hw));
            asm volatile("st.shared.v4.b32 [%0], {%1,%2,%3,%4};" ::
                         "r"(sb_hi + i * 16), "r"(hx), "r"(hy), "r"(hz), "r"(hw) : "memory");
            asm volatile("st.shared.v4.b32 [%0], {%1,%2,%3,%4};" ::
                         "r"(sb_lo + i * 16), "r"(lx), "r"(ly), "r"(lz), "r"(lw) : "memory");
        }
        __syncthreads();

#pragma unroll
        for (int k8 = 0; k8 < 4; k8++) {
            uint32_t kb = (uint32_t)(k8 * 32);
            uint32_t Ah[4][4], Al[4][4], Bh[2][4], Bl[2][4];
#pragma unroll
            for (int mt = 0; mt < 4; mt++) {
                uint32_t addr = mybuf + (mt * 16 + a_row) * 144 + kb + a_colb;
                ldsm4(Ah[mt], addr);
                ldsm4(Al[mt], addr + 64 * 144);
            }
#pragma unroll
            for (int nh = 0; nh < 2; nh++) {
                uint32_t addr = mybuf + (ncol + nh * 16 + b_row) * 144 + kb + b_colb;
                ldsm4(Bh[nh], addr);
                ldsm4(Bl[nh], addr + 64 * 144);
            }
#pragma unroll
            for (int mt = 0; mt < 4; mt++)
#pragma unroll
                for (int nt = 0; nt < 4; nt++) {
                    const uint32_t* bh = &Bh[nt >> 1][(nt & 1) * 2];
                    const uint32_t* bl = &Bl[nt >> 1][(nt & 1) * 2];
                    mma8(acc[mt][nt], Ah[mt], bh);   // hi*hi
                    mma8(acc[mt][nt], Ah[mt], bl);   // hi*lo
                    mma8(acc[mt][nt], Al[mt], bh);   // lo*hi
                }
        }
    }

    // channel sums: tid pairs (sc, sj=0/1) share a channel
    csum += __shfl_xor_sync(0xffffffffu, csum, 1);
    if (sj == 0)
        g_sums_part[((mat * NB + n) * SPLITS + split) * 64 + sc] = csum;

    // in-block substream reduce: warps wk=1 dump to smem, wk=0 add + write
    __syncthreads();
    float* sred = (float*)sY;   // [wn][64][32]
    if (wk == 1) {
        float* dst = sred + wn * 2048;
#pragma unroll
        for (int i = 0; i < 64; i++)
            dst[i * 32 + lane] = acc[i >> 4][(i >> 2) & 3][i & 3];
    }
    __syncthreads();
    if (wk == 0) {
        const float* s2 = sred + wn * 2048;
#pragma unroll
        for (int i = 0; i < 64; i++)
            acc[i >> 4][(i >> 2) & 3][i & 3] += s2[i * 32 + lane];

        float* gb = g_gram_part + ((mat * NB + n) * SPLITS + split) * 4096;
        int gr = lane >> 2, tig = lane & 3;
#pragma unroll
        for (int mt = 0; mt < 4; mt++)
#pragma unroll
            for (int nt = 0; nt < 4; nt++) {
                int row = mt * 16 + gr;
                int col = ncol + nt * 8 + 2 * tig;
                *(float2*)&gb[row * 64 + col] =
                    make_float2(acc[mt][nt][0], acc[mt][nt][1]);
                *(float2*)&gb[(row + 8) * 64 + col] =
                    make_float2(acc[mt][nt][2], acc[mt][nt][3]);
            }
    }
}

// ---------------------------------------------------------------------------
// Kernel 2: logits  S = W G W^T + b u^T + u b^T + WH b b^T   (per n, per mat)
// grid = 32, 256 threads. Reduces 32 gram partials + 32 sum partials.
// ---------------------------------------------------------------------------
__global__ void __launch_bounds__(256) logits_kernel(const float* __restrict__ WR,
                                                     const float* __restrict__ bR,
                                                     const float* __restrict__ WT,
                                                     const float* __restrict__ bT) {
    int n = blockIdx.x & 15;
    int mat = blockIdx.x >> 4;
    const float* W  = mat ? WT : WR;
    const float* bv = mat ? bT : bR;

    __shared__ float sW[64][64];
    __shared__ float sGM[64][65];
    __shared__ float sb[64], ssum[64], su[64];

    int tid = threadIdx.x;
    for (int i = tid; i < 1024; i += 256)
        ((float4*)&sW[0][0])[i] = ((const float4*)W)[i];

    const float4* gp = (const float4*)(g_gram_part + (mat * NB + n) * SPLITS * 4096);
    for (int i = tid; i < 1024; i += 256) {
        float4 a = gp[i];
#pragma unroll
        for (int s = 1; s < SPLITS; s++) {
            float4 b = gp[s * 1024 + i];
            a.x += b.x; a.y += b.y; a.z += b.z; a.w += b.w;
        }
        int row = i >> 4, col = (i & 15) * 4;
        sGM[row][col] = a.x; sGM[row][col + 1] = a.y;
        sGM[row][col + 2] = a.z; sGM[row][col + 3] = a.w;
    }
    if (tid < 64) {
        sb[tid] = bv[tid];
        const float* sp = g_sums_part + (mat * NB + n) * SPLITS * 64 + tid;
        float s = 0.0f;
#pragma unroll
        for (int k = 0; k < SPLITS; k++) s += sp[k * 64];
        ssum[tid] = s;
    }
    __syncthreads();

    if (tid < 64) {
        float u = 0.0f;
        for (int f = 0; f < 64; f++) u += sW[tid][f] * ssum[f];
        su[tid] = u;
    }

    int r = tid >> 4, q = tid & 15;
    float acc[4][4];
#pragma unroll
    for (int i = 0; i < 4; i++)
#pragma unroll
        for (int j = 0; j < 4; j++) acc[i][j] = 0.0f;
    for (int f = 0; f < 64; f++) {
        float wv[4], gv[4];
#pragma unroll
        for (int i = 0; i < 4; i++) wv[i] = sW[4 * r + i][f];
#pragma unroll
        for (int j = 0; j < 4; j++) gv[j] = sGM[f][4 * q + j];
#pragma unroll
        for (int i = 0; i < 4; i++)
#pragma unroll
            for (int j = 0; j < 4; j++) acc[i][j] = fmaf(wv[i], gv[j], acc[i][j]);
    }
    __syncthreads();
#pragma unroll
    for (int i = 0; i < 4; i++)
#pragma unroll
        for (int j = 0; j < 4; j++) sGM[4 * r + i][4 * q + j] = acc[i][j];
    __syncthreads();

#pragma unroll
    for (int i = 0; i < 4; i++)
#pragma unroll
        for (int j = 0; j < 4; j++) acc[i][j] = 0.0f;
    for (int e = 0; e < 64; e++) {
        float mv[4], wv[4];
#pragma unroll
        for (int i = 0; i < 4; i++) mv[i] = sGM[4 * r + i][e];
#pragma unroll
        for (int j = 0; j < 4; j++) wv[j] = sW[4 * q + j][e];
#pragma unroll
        for (int i = 0; i < 4; i++)
#pragma unroll
            for (int j = 0; j < 4; j++) acc[i][j] = fmaf(mv[i], wv[j], acc[i][j]);
    }

    float* lbase = g_logits + n * (2 * CC * CC);
#pragma unroll
    for (int i = 0; i < 4; i++) {
        int ci = 4 * r + i;
#pragma unroll
        for (int j = 0; j < 4; j++) {
            int dj = 4 * q + j;
            float L = acc[i][j] + sb[ci] * su[dj] + su[ci] * sb[dj]
                    + 16384.0f * sb[ci] * sb[dj];
            lbase[(mat * CC + ci) * CC + dj] = L;
        }
    }
}

// ---------------------------------------------------------------------------
// Kernel 3: softmax over 128 rows per (n, col). grid = 16, 256 threads.
// ---------------------------------------------------------------------------
__global__ void __launch_bounds__(256) softmax_kernel() {
    __shared__ float sE[128][64];
    __shared__ float sred[256];

    int n = blockIdx.x;
    int tid = threadIdx.x;
    int col = tid & 63, q = tid >> 6;
    const float* L = g_logits + n * 8192;

    float m = -3.0e38f;
    for (int k = 32 * q; k < 32 * q + 32; k++) {
        float v = L[k * 64 + col];
        sE[k][col] = v;
        m = fmaxf(m, v);
    }
    sred[tid] = m;
    __syncthreads();
    m = fmaxf(fmaxf(sred[col], sred[64 + col]),
              fmaxf(sred[128 + col], sred[192 + col]));
    __syncthreads();

    float s = 0.0f;
    for (int k = 32 * q; k < 32 * q + 32; k++) {
        float e = __expf(sE[k][col] - m);
        sE[k][col] = e;
        s += e;
    }
    sred[tid] = s;
    __syncthreads();
    s = (sred[col] + sred[64 + col]) + (sred[128 + col] + sred[192 + col]);
    float inv = 1.0f / s;

    float* A = g_att + n * 8192;
    for (int k = 32 * q; k < 32 * q + 32; k++)
        A[k * 64 + col] = sE[k][col] * inv;
}

// ---------------------------------------------------------------------------
// Kernel 4: out[n,c,p] = sum_k xcat[n,k,p] * att[n,k,c]  (FFMA2 path)
// ---------------------------------------------------------------------------
__global__ void __launch_bounds__(256) out_kernel(const float* __restrict__ xR,
                                                  const float* __restrict__ xT,
                                                  float* __restrict__ out) {
    int n  = blockIdx.y;
    int pb = blockIdx.x * 256;

    __shared__ float att_s[128][64];
    __shared__ float xs[16][256];

    int tid = threadIdx.x;
    const float4* attp = (const float4*)(g_att + n * (2 * CC * CC));
#pragma unroll
    for (int i = 0; i < 8; i++)
        ((float4*)&att_s[0][0])[tid + i * 256] = attp[tid + i * 256];

    int ci = tid >> 5;
    int pj = tid & 31;
    int kl = tid >> 4;
    int pc = (tid & 15) * 16;

    u64 acc[8][4];
#pragma unroll
    for (int i = 0; i < 8; i++)
#pragma unroll
        for (int s = 0; s < 4; s++) acc[i][s] = 0ull;

    const float* baseR = xR + n * CWH + pb;
    const float* baseT = xT + n * CWH + pb;

    float4 v[4];
    {
        const float* srcp = baseR + kl * WHT + pc;
#pragma unroll
        for (int i = 0; i < 4; i++) v[i] = *(const float4*)(srcp + 4 * i);
    }

    for (int kt = 0; kt < 8; kt++) {
        __syncthreads();
#pragma unroll
        for (int i = 0; i < 4; i++)
            *(float4*)&xs[kl][pc + 4 * i] = v[i];
        __syncthreads();
        if (kt < 7) {
            int kt2 = kt + 1;
            const float* src = (kt2 < 4) ? baseR : baseT;
            int kbase = (kt2 < 4) ? kt2 * 16 : (kt2 - 4) * 16;
            const float* srcp = src + (kbase + kl) * WHT + pc;
#pragma unroll
            for (int i = 0; i < 4; i++) v[i] = *(const float4*)(srcp + 4 * i);
        }
#pragma unroll 8
        for (int k = 0; k < 16; k++) {
            const float* ar = att_s[kt * 16 + k];
            float4 a0 = *(const float4*)&ar[8 * ci];
            float4 a1 = *(const float4*)&ar[8 * ci + 4];
            const float* xr = xs[k];
            u64 B0 = *(const u64*)&xr[2 * pj];
            u64 B1 = *(const u64*)&xr[2 * pj + 64];
            u64 B2 = *(const u64*)&xr[2 * pj + 128];
            u64 B3 = *(const u64*)&xr[2 * pj + 192];
            u64 A;
            A = splat2(a0.x); ffma2(acc[0][0],A,B0); ffma2(acc[0][1],A,B1); ffma2(acc[0][2],A,B2); ffma2(acc[0][3],A,B3);
            A = splat2(a0.y); ffma2(acc[1][0],A,B0); ffma2(acc[1][1],A,B1); ffma2(acc[1][2],A,B2); ffma2(acc[1][3],A,B3);
            A = splat2(a0.z); ffma2(acc[2][0],A,B0); ffma2(acc[2][1],A,B1); ffma2(acc[2][2],A,B2); ffma2(acc[2][3],A,B3);
            A = splat2(a0.w); ffma2(acc[3][0],A,B0); ffma2(acc[3][1],A,B1); ffma2(acc[3][2],A,B2); ffma2(acc[3][3],A,B3);
            A = splat2(a1.x); ffma2(acc[4][0],A,B0); ffma2(acc[4][1],A,B1); ffma2(acc[4][2],A,B2); ffma2(acc[4][3],A,B3);
            A = splat2(a1.y); ffma2(acc[5][0],A,B0); ffma2(acc[5][1],A,B1); ffma2(acc[5][2],A,B2); ffma2(acc[5][3],A,B3);
            A = splat2(a1.z); ffma2(acc[6][0],A,B0); ffma2(acc[6][1],A,B1); ffma2(acc[6][2],A,B2); ffma2(acc[6][3],A,B3);
            A = splat2(a1.w); ffma2(acc[7][0],A,B0); ffma2(acc[7][1],A,B1); ffma2(acc[7][2],A,B2); ffma2(acc[7][3],A,B3);
        }
    }

    float* ob = out + n * CWH + pb;
#pragma unroll
    for (int i = 0; i < 8; i++) {
        int c = 8 * ci + i;
#pragma unroll
        for (int s = 0; s < 4; s++) {
            float2 w = unpk(acc[i][s]);
            *(float2*)&ob[c * WHT + 2 * pj + 64 * s] = w;
        }
    }
}

// ---------------------------------------------------------------------------
extern "C" void kernel_launch(void* const* d_in, const int* in_sizes, int n_in,
                              void* d_out, int out_size) {
    const float* xR = (const float*)d_in[0];
    const float* xT = (const float*)d_in[1];
    const float* WR = (const float*)d_in[2];
    const float* bR = (const float*)d_in[3];
    const float* WT = (const float*)d_in[4];
    const float* bT = (const float*)d_in[5];
    float* out = (float*)d_out;

    gram_mma_kernel<<<2 * NB * SPLITS, 128>>>(xR, xT);
    logits_kernel<<<2 * NB, 256>>>(WR, bR, WT, bT);
    softmax_kernel<<<NB, 256>>>();
    out_kernel<<<dim3(WHT / 256, NB), 256>>>(xR, xT, out);
}

// round 7
// speedup vs baseline: 1.5822x; 1.2523x over previous
#include <cuda_runtime.h>
#include <cuda_bf16.h>
#include <cstdint>

#define NB     16
#define CC     64
#define WHT    16384
#define CWH    (CC * WHT)
#define SPLITS 32

// Scratch (device globals; allocation is forbidden)
__device__ float g_gram_part[2 * NB * SPLITS * CC * CC];
__device__ float g_sums_part[2 * NB * SPLITS * CC];
__device__ float g_logits[NB * 2 * CC * CC];
__device__ float g_att[NB * 2 * CC * CC];

typedef unsigned long long u64;

__device__ __forceinline__ uint32_t smem_u32(const void* p) {
    uint32_t a;
    asm("{ .reg .u64 t; cvta.to.shared.u64 t, %1; cvt.u32.u64 %0, t; }" : "=r"(a) : "l"(p));
    return a;
}
__device__ __forceinline__ uint32_t cvt_tf32(float x) {
    uint32_t r;
    asm("cvt.rna.tf32.f32 %0, %1;" : "=r"(r) : "f"(x));
    return r;
}
__device__ __forceinline__ void ldsm4(uint32_t* r, uint32_t addr) {
    asm volatile("ldmatrix.sync.aligned.m8n8.x4.shared.b16 {%0,%1,%2,%3}, [%4];"
                 : "=r"(r[0]), "=r"(r[1]), "=r"(r[2]), "=r"(r[3]) : "r"(addr));
}
__device__ __forceinline__ void ldsm4t(uint32_t* r, uint32_t addr) {
    asm volatile("ldmatrix.sync.aligned.m8n8.x4.trans.shared.b16 {%0,%1,%2,%3}, [%4];"
                 : "=r"(r[0]), "=r"(r[1]), "=r"(r[2]), "=r"(r[3]) : "r"(addr));
}
__device__ __forceinline__ void mma8(float* d, const uint32_t* a, const uint32_t* b) {
    asm volatile(
        "mma.sync.aligned.m16n8k8.row.col.f32.tf32.tf32.f32 "
        "{%0,%1,%2,%3}, {%4,%5,%6,%7}, {%8,%9}, {%0,%1,%2,%3};"
        : "+f"(d[0]), "+f"(d[1]), "+f"(d[2]), "+f"(d[3])
        : "r"(a[0]), "r"(a[1]), "r"(a[2]), "r"(a[3]), "r"(b[0]), "r"(b[1]));
}
__device__ __forceinline__ void mma16bf(float* d, const uint32_t* a, const uint32_t* b) {
    asm volatile(
        "mma.sync.aligned.m16n8k16.row.col.f32.bf16.bf16.f32 "
        "{%0,%1,%2,%3}, {%4,%5,%6,%7}, {%8,%9}, {%0,%1,%2,%3};"
        : "+f"(d[0]), "+f"(d[1]), "+f"(d[2]), "+f"(d[3])
        : "r"(a[0]), "r"(a[1]), "r"(a[2]), "r"(a[3]), "r"(b[0]), "r"(b[1]));
}
// pack two f32 -> bf16x2 (lo = e0, hi = e1)
__device__ __forceinline__ uint32_t pack_bf16x2(float e0, float e1) {
    uint32_t r;
    asm("cvt.rn.bf16x2.f32 %0, %1, %2;" : "=r"(r) : "f"(e1), "f"(e0));
    return r;
}
__device__ __forceinline__ float bf16hi_f32(float x) {
    // exact f32 value of bf16_rn(x)
    __nv_bfloat16 b = __float2bfloat16_rn(x);
    return __bfloat162float(b);
}

// ---------------------------------------------------------------------------
// Kernel 1: gram partials via mma.sync tf32 with hi/lo splitting. (unchanged)
// ---------------------------------------------------------------------------
__global__ void __launch_bounds__(128) gram_mma_kernel(const float* __restrict__ xR,
                                                       const float* __restrict__ xT) {
    int bid = blockIdx.x;
    int split = bid & 31;
    int n = (bid >> 5) & 15;
    int mat = bid >> 9;
    const float* src = (mat ? xT : xR) + n * CWH;

    __shared__ uint32_t sY[2][128 * 36];

    int tid = threadIdx.x;
    int w = tid >> 5;
    int lane = tid & 31;
    int wk = w >> 1;
    int wn = w & 1;
    int ncol = wn * 32;

    int sc = tid >> 1;
    int sj = tid & 1;
    const float* gsrc = src + sc * WHT + split * 512 + sj * 32;

    int q  = lane >> 3;
    int r8 = lane & 7;
    int a_row  = r8 + ((q & 1) << 3);
    int a_colb = (q >> 1) << 4;
    int b_row  = r8 + ((q >> 1) << 3);
    int b_colb = (q & 1) << 4;

    float acc[4][4][4];
#pragma unroll
    for (int i = 0; i < 4; i++)
#pragma unroll
        for (int j = 0; j < 4; j++)
#pragma unroll
            for (int c = 0; c < 4; c++) acc[i][j][c] = 0.0f;
    float csum = 0.0f;

    uint32_t buf0 = smem_u32(sY[0]);
    uint32_t buf1 = smem_u32(sY[1]);
    uint32_t mybuf = wk ? buf1 : buf0;
    uint32_t stbuf = sj ? buf1 : buf0;
    uint32_t sb_hi = stbuf + sc * 144;
    uint32_t sb_lo = sb_hi + 64 * 144;

#pragma unroll 1
    for (int t = 0; t < 8; t++) {
        __syncthreads();
        const float4* p = (const float4*)(gsrc + t * 64);
#pragma unroll
        for (int i = 0; i < 8; i++) {
            float4 v = p[i];
            csum += (v.x + v.y) + (v.z + v.w);
            uint32_t hx = cvt_tf32(v.x), hy = cvt_tf32(v.y);
            uint32_t hz = cvt_tf32(v.z), hw = cvt_tf32(v.w);
            uint32_t lx = cvt_tf32(v.x - __uint_as_float(hx));
            uint32_t ly = cvt_tf32(v.y - __uint_as_float(hy));
            uint32_t lz = cvt_tf32(v.z - __uint_as_float(hz));
            uint32_t lw = cvt_tf32(v.w - __uint_as_float(hw));
            asm volatile("st.shared.v4.b32 [%0], {%1,%2,%3,%4};" ::
                         "r"(sb_hi + i * 16), "r"(hx), "r"(hy), "r"(hz), "r"(hw) : "memory");
            asm volatile("st.shared.v4.b32 [%0], {%1,%2,%3,%4};" ::
                         "r"(sb_lo + i * 16), "r"(lx), "r"(ly), "r"(lz), "r"(lw) : "memory");
        }
        __syncthreads();

#pragma unroll
        for (int k8 = 0; k8 < 4; k8++) {
            uint32_t kb = (uint32_t)(k8 * 32);
            uint32_t Ah[4][4], Al[4][4], Bh[2][4], Bl[2][4];
#pragma unroll
            for (int mt = 0; mt < 4; mt++) {
                uint32_t addr = mybuf + (mt * 16 + a_row) * 144 + kb + a_colb;
                ldsm4(Ah[mt], addr);
                ldsm4(Al[mt], addr + 64 * 144);
            }
#pragma unroll
            for (int nh = 0; nh < 2; nh++) {
                uint32_t addr = mybuf + (ncol + nh * 16 + b_row) * 144 + kb + b_colb;
                ldsm4(Bh[nh], addr);
                ldsm4(Bl[nh], addr + 64 * 144);
            }
#pragma unroll
            for (int mt = 0; mt < 4; mt++)
#pragma unroll
                for (int nt = 0; nt < 4; nt++) {
                    const uint32_t* bh = &Bh[nt >> 1][(nt & 1) * 2];
                    const uint32_t* bl = &Bl[nt >> 1][(nt & 1) * 2];
                    mma8(acc[mt][nt], Ah[mt], bh);
                    mma8(acc[mt][nt], Ah[mt], bl);
                    mma8(acc[mt][nt], Al[mt], bh);
                }
        }
    }

    csum += __shfl_xor_sync(0xffffffffu, csum, 1);
    if (sj == 0)
        g_sums_part[((mat * NB + n) * SPLITS + split) * 64 + sc] = csum;

    __syncthreads();
    float* sred = (float*)sY;
    if (wk == 1) {
        float* dst = sred + wn * 2048;
#pragma unroll
        for (int i = 0; i < 64; i++)
            dst[i * 32 + lane] = acc[i >> 4][(i >> 2) & 3][i & 3];
    }
    __syncthreads();
    if (wk == 0) {
        const float* s2 = sred + wn * 2048;
#pragma unroll
        for (int i = 0; i < 64; i++)
            acc[i >> 4][(i >> 2) & 3][i & 3] += s2[i * 32 + lane];

        float* gb = g_gram_part + ((mat * NB + n) * SPLITS + split) * 4096;
        int gr = lane >> 2, tig = lane & 3;
#pragma unroll
        for (int mt = 0; mt < 4; mt++)
#pragma unroll
            for (int nt = 0; nt < 4; nt++) {
                int row = mt * 16 + gr;
                int col = ncol + nt * 8 + 2 * tig;
                *(float2*)&gb[row * 64 + col] =
                    make_float2(acc[mt][nt][0], acc[mt][nt][1]);
                *(float2*)&gb[(row + 8) * 64 + col] =
                    make_float2(acc[mt][nt][2], acc[mt][nt][3]);
            }
    }
}

// ---------------------------------------------------------------------------
// Kernel 2: logits (unchanged)
// ---------------------------------------------------------------------------
__global__ void __launch_bounds__(256) logits_kernel(const float* __restrict__ WR,
                                                     const float* __restrict__ bR,
                                                     const float* __restrict__ WT,
                                                     const float* __restrict__ bT) {
    int n = blockIdx.x & 15;
    int mat = blockIdx.x >> 4;
    const float* W  = mat ? WT : WR;
    const float* bv = mat ? bT : bR;

    __shared__ float sW[64][64];
    __shared__ float sGM[64][65];
    __shared__ float sb[64], ssum[64], su[64];

    int tid = threadIdx.x;
    for (int i = tid; i < 1024; i += 256)
        ((float4*)&sW[0][0])[i] = ((const float4*)W)[i];

    const float4* gp = (const float4*)(g_gram_part + (mat * NB + n) * SPLITS * 4096);
    for (int i = tid; i < 1024; i += 256) {
        float4 a = gp[i];
#pragma unroll
        for (int s = 1; s < SPLITS; s++) {
            float4 b = gp[s * 1024 + i];
            a.x += b.x; a.y += b.y; a.z += b.z; a.w += b.w;
        }
        int row = i >> 4, col = (i & 15) * 4;
        sGM[row][col] = a.x; sGM[row][col + 1] = a.y;
        sGM[row][col + 2] = a.z; sGM[row][col + 3] = a.w;
    }
    if (tid < 64) {
        sb[tid] = bv[tid];
        const float* sp = g_sums_part + (mat * NB + n) * SPLITS * 64 + tid;
        float s = 0.0f;
#pragma unroll
        for (int k = 0; k < SPLITS; k++) s += sp[k * 64];
        ssum[tid] = s;
    }
    __syncthreads();

    if (tid < 64) {
        float u = 0.0f;
        for (int f = 0; f < 64; f++) u += sW[tid][f] * ssum[f];
        su[tid] = u;
    }

    int r = tid >> 4, q = tid & 15;
    float acc[4][4];
#pragma unroll
    for (int i = 0; i < 4; i++)
#pragma unroll
        for (int j = 0; j < 4; j++) acc[i][j] = 0.0f;
    for (int f = 0; f < 64; f++) {
        float wv[4], gv[4];
#pragma unroll
        for (int i = 0; i < 4; i++) wv[i] = sW[4 * r + i][f];
#pragma unroll
        for (int j = 0; j < 4; j++) gv[j] = sGM[f][4 * q + j];
#pragma unroll
        for (int i = 0; i < 4; i++)
#pragma unroll
            for (int j = 0; j < 4; j++) acc[i][j] = fmaf(wv[i], gv[j], acc[i][j]);
    }
    __syncthreads();
#pragma unroll
    for (int i = 0; i < 4; i++)
#pragma unroll
        for (int j = 0; j < 4; j++) sGM[4 * r + i][4 * q + j] = acc[i][j];
    __syncthreads();

#pragma unroll
    for (int i = 0; i < 4; i++)
#pragma unroll
        for (int j = 0; j < 4; j++) acc[i][j] = 0.0f;
    for (int e = 0; e < 64; e++) {
        float mv[4], wv[4];
#pragma unroll
        for (int i = 0; i < 4; i++) mv[i] = sGM[4 * r + i][e];
#pragma unroll
        for (int j = 0; j < 4; j++) wv[j] = sW[4 * q + j][e];
#pragma unroll
        for (int i = 0; i < 4; i++)
#pragma unroll
            for (int j = 0; j < 4; j++) acc[i][j] = fmaf(mv[i], wv[j], acc[i][j]);
    }

    float* lbase = g_logits + n * (2 * CC * CC);
#pragma unroll
    for (int i = 0; i < 4; i++) {
        int ci = 4 * r + i;
#pragma unroll
        for (int j = 0; j < 4; j++) {
            int dj = 4 * q + j;
            float L = acc[i][j] + sb[ci] * su[dj] + su[ci] * sb[dj]
                    + 16384.0f * sb[ci] * sb[dj];
            lbase[(mat * CC + ci) * CC + dj] = L;
        }
    }
}

// ---------------------------------------------------------------------------
// Kernel 3: softmax (unchanged)
// ---------------------------------------------------------------------------
__global__ void __launch_bounds__(256) softmax_kernel() {
    __shared__ float sE[128][64];
    __shared__ float sred[256];

    int n = blockIdx.x;
    int tid = threadIdx.x;
    int col = tid & 63, q = tid >> 6;
    const float* L = g_logits + n * 8192;

    float m = -3.0e38f;
    for (int k = 32 * q; k < 32 * q + 32; k++) {
        float v = L[k * 64 + col];
        sE[k][col] = v;
        m = fmaxf(m, v);
    }
    sred[tid] = m;
    __syncthreads();
    m = fmaxf(fmaxf(sred[col], sred[64 + col]),
              fmaxf(sred[128 + col], sred[192 + col]));
    __syncthreads();

    float s = 0.0f;
    for (int k = 32 * q; k < 32 * q + 32; k++) {
        float e = __expf(sE[k][col] - m);
        sE[k][col] = e;
        s += e;
    }
    sred[tid] = s;
    __syncthreads();
    s = (sred[col] + sred[64 + col]) + (sred[128 + col] + sred[192 + col]);
    float inv = 1.0f / s;

    float* A = g_att + n * 8192;
    for (int k = 32 * q; k < 32 * q + 32; k++)
        A[k * 64 + col] = sE[k][col] * inv;
}

// ---------------------------------------------------------------------------
// Kernel 4: out via bf16 mma.sync m16n8k16, 3-stream split.
// grid = (WHT/256, NB), 128 threads (4 warps). Warp tile: 64 px x 64 c.
// D[p][c] = sum_k x^T[p][k] att[k][c]:  A = x (trans-ldsm), B = att (trans-ldsm).
// x staged [k32][p256] bf16 per chunk; att [k128][c64] bf16, both b1/b2 splits.
// Dynamic smem: attb1 | attb2 | xb1 | xb2 = 18432 + 18432 + 16896 + 16896.
// ---------------------------------------------------------------------------
#define OSM_ATT1 0
#define OSM_ATT2 18432
#define OSM_X1   36864
#define OSM_X2   53760
#define OSM_TOT  70656

__global__ void __launch_bounds__(128) out_mma_kernel(const float* __restrict__ xR,
                                                      const float* __restrict__ xT,
                                                      float* __restrict__ out) {
    extern __shared__ __align__(16) char osm[];
    uint32_t sb = smem_u32(osm);

    int n  = blockIdx.y;
    int pb = blockIdx.x * 256;
    int tid = threadIdx.x;
    int w = tid >> 5;
    int lane = tid & 31;

    // ---- stage att: [k 128][c 64] -> bf16 splits, stride 144B ----
    {
        const float2* attp = (const float2*)(g_att + n * 8192);
#pragma unroll
        for (int i = 0; i < 32; i++) {
            int f2 = tid + i * 128;
            int k = f2 >> 5, c2 = f2 & 31;
            float2 v = attp[f2];
            float h0 = bf16hi_f32(v.x), h1 = bf16hi_f32(v.y);
            uint32_t p1 = pack_bf16x2(h0, h1);
            uint32_t p2 = pack_bf16x2(v.x - h0, v.y - h1);
            uint32_t a = sb + k * 144 + c2 * 4;
            asm volatile("st.shared.b32 [%0], %1;" :: "r"(a + OSM_ATT1), "r"(p1) : "memory");
            asm volatile("st.shared.b32 [%0], %1;" :: "r"(a + OSM_ATT2), "r"(p2) : "memory");
        }
    }

    // lane addressing for trans ldmatrix
    int aK  = (lane & 7) + ((lane >> 4) << 3);   // A: k row
    int aP  = ((lane >> 3) & 1) << 3;            // A: +8 px
    int bK  = lane & 15;                         // B: k row
    int bC  = (lane >> 4) << 3;                  // B: +8 c

    int p0w = w * 64;

    float acc[4][8][4];
#pragma unroll
    for (int i = 0; i < 4; i++)
#pragma unroll
        for (int j = 0; j < 8; j++)
#pragma unroll
            for (int c = 0; c < 4; c++) acc[i][j][c] = 0.0f;

    const float* baseR = xR + n * CWH + pb;
    const float* baseT = xT + n * CWH + pb;

#pragma unroll 1
    for (int half = 0; half < 2; half++) {
        const float* xsrc = half ? baseT : baseR;
#pragma unroll 1
        for (int chunk = 0; chunk < 2; chunk++) {
            // ---- stage x chunk: [k 32][p 256] bf16 splits, stride 528B ----
            __syncthreads();
            const float* cs = xsrc + (chunk * 32) * WHT;
#pragma unroll
            for (int i = 0; i < 16; i++) {
                int fq = tid + i * 128;
                int kr = fq >> 6, pq = fq & 63;
                float4 v = *(const float4*)(cs + kr * WHT + pq * 4);
                float h0 = bf16hi_f32(v.x), h1 = bf16hi_f32(v.y);
                float h2 = bf16hi_f32(v.z), h3 = bf16hi_f32(v.w);
                uint32_t q10 = pack_bf16x2(h0, h1);
                uint32_t q11 = pack_bf16x2(h2, h3);
                uint32_t q20 = pack_bf16x2(v.x - h0, v.y - h1);
                uint32_t q21 = pack_bf16x2(v.z - h2, v.w - h3);
                uint32_t a = sb + kr * 528 + pq * 8;
                asm volatile("st.shared.v2.b32 [%0], {%1,%2};" ::
                             "r"(a + OSM_X1), "r"(q10), "r"(q11) : "memory");
                asm volatile("st.shared.v2.b32 [%0], {%1,%2};" ::
                             "r"(a + OSM_X2), "r"(q20), "r"(q21) : "memory");
            }
            __syncthreads();

#pragma unroll
            for (int k16 = 0; k16 < 2; k16++) {
                int kg = half * 64 + chunk * 32 + k16 * 16;   // global k for att
                // B fragments: 4 ldsm x4 per split -> 8 n-tiles
                uint32_t B1[4][4], B2[4][4];
#pragma unroll
                for (int nq = 0; nq < 4; nq++) {
                    uint32_t a = sb + (kg + bK) * 144 + (nq * 16 + bC) * 2;
                    ldsm4t(B1[nq], a + OSM_ATT1);
                    ldsm4t(B2[nq], a + OSM_ATT2);
                }
#pragma unroll
                for (int mt = 0; mt < 4; mt++) {
                    uint32_t A1[4], A2[4];
                    uint32_t a = sb + (k16 * 16 + aK) * 528
                               + (p0w + mt * 16 + aP) * 2;
                    ldsm4t(A1, a + OSM_X1);
                    ldsm4t(A2, a + OSM_X2);
#pragma unroll
                    for (int nq = 0; nq < 4; nq++)
#pragma unroll
                        for (int s = 0; s < 2; s++) {
                            const uint32_t* b1 = &B1[nq][s * 2];
                            const uint32_t* b2 = &B2[nq][s * 2];
                            float* d = acc[mt][nq * 2 + s];
                            mma16bf(d, A1, b1);   // a1*x1
                            mma16bf(d, A2, b1);   // a2*x1 (A=x: x2*a1)
                            mma16bf(d, A1, b2);   // a1*x2
                        }
                }
            }
        }
    }

    // ---- epilogue: D[p][c] -> out[c][p] ----
    float* ob = out + n * CWH + pb;
    int pr = lane >> 2;
    int cr = (lane & 3) * 2;
#pragma unroll
    for (int mt = 0; mt < 4; mt++) {
        int p = p0w + mt * 16 + pr;
#pragma unroll
        for (int nt = 0; nt < 8; nt++) {
            int c = nt * 8 + cr;
            float* d = acc[mt][nt];
            ob[c * WHT + p]           = d[0];
            ob[(c + 1) * WHT + p]     = d[1];
            ob[c * WHT + p + 8]       = d[2];
            ob[(c + 1) * WHT + p + 8] = d[3];
        }
    }
}

// ---------------------------------------------------------------------------
extern "C" void kernel_launch(void* const* d_in, const int* in_sizes, int n_in,
                              void* d_out, int out_size) {
    const float* xR = (const float*)d_in[0];
    const float* xT = (const float*)d_in[1];
    const float* WR = (const float*)d_in[2];
    const float* bR = (const float*)d_in[3];
    const float* WT = (const float*)d_in[4];
    const float* bT = (const float*)d_in[5];
    float* out = (float*)d_out;

    cudaFuncSetAttribute(out_mma_kernel,
                         cudaFuncAttributeMaxDynamicSharedMemorySize, OSM_TOT);

    gram_mma_kernel<<<2 * NB * SPLITS, 128>>>(xR, xT);
    logits_kernel<<<2 * NB, 256>>>(WR, bR, WT, bT);
    softmax_kernel<<<NB, 256>>>();
    out_mma_kernel<<<dim3(WHT / 256, NB), 128, OSM_TOT>>>(xR, xT, out);
}